// round 2
// baseline (speedup 1.0000x reference)
#include <cuda_runtime.h>
#include <mma.h>
#include <cstdint>
#include <math.h>

using namespace nvcuda;

#define E_BONDS   131072
#define N_ATOMS_  65536
#define HID       256
#define AFD       143
#define KIN       157     // AFD + BOND_FDIM(14)
#define KCAT      399     // AFD + HID
#define BMOL      2048

#define EH  ((size_t)E_BONDS * HID)
#define NH  ((size_t)N_ATOMS_ * HID)
__device__ float g_scratch[3 * (size_t)E_BONDS * HID + 4 * (size_t)N_ATOMS_ * HID];

// ---------------------------------------------------------------------------
__device__ __forceinline__ float to_tf32(float x) {
    float r; asm("cvt.rna.tf32.f32 %0, %1;\n" : "=f"(r) : "f"(x)); return r;
}
__device__ __forceinline__ float4 f4add(float4 a, float4 b) {
    return make_float4(a.x + b.x, a.y + b.y, a.z + b.z, a.w + b.w);
}
__device__ __forceinline__ float4 f4fma(float s, float4 a, float4 acc) {
    acc.x += s * a.x; acc.y += s * a.y; acc.z += s * a.z; acc.w += s * a.w;
    return acc;
}
__device__ __forceinline__ float f4dot(float4 a, float4 b) {
    return a.x * b.x + a.y * b.y + a.z * b.z + a.w * b.w;
}

// ---------------------------------------------------------------------------
// tf32 tensor-core GEMM: C[M,256] = A[M,K] @ B[K,256] (+D)(+bias)(relu)(raw)
// Block tile 128x128 (grid.y=2 covers N=256), 256 threads, warp tile 32x64.
// CONCAT: A columns [0,K1) from A1 (lda), [K1,K) from A2 (ld 256).
// ---------------------------------------------------------------------------
#define LDA_S 36    // 32 + 4 pad
#define LDB_S 132   // 128 + 4 pad
#define LDC_S 68    // 64 + 4 pad

template<bool CONCAT, bool HAS_D, bool HAS_BIAS, bool RELU, bool HAS_RAW>
__global__ void __launch_bounds__(256) tgemm128(
    int M, int K, int K1,
    const float* __restrict__ A, int lda,
    const float* __restrict__ A2,
    const float* __restrict__ B,
    const float* __restrict__ D,
    const float* __restrict__ bias,
    float* __restrict__ out,
    float* __restrict__ raw)
{
    __shared__ float smem[8832];            // sA 128*36=4608 | sB 32*132=4224
    float* sA = smem;
    float* sB = smem + 4608;

    const int tid    = threadIdx.x;
    const int lane   = tid & 31;
    const int wid    = tid >> 5;
    const int warp_m = wid & 3;             // 0..3 -> 32-row slabs
    const int warp_n = wid >> 2;            // 0..1 -> 64-col slabs
    const int m0     = blockIdx.x * 128;
    const int n0     = blockIdx.y * 128;

    wmma::fragment<wmma::accumulator, 16, 16, 8, float> acc[2][4];
#pragma unroll
    for (int i = 0; i < 2; i++)
#pragma unroll
        for (int j = 0; j < 4; j++) wmma::fill_fragment(acc[i][j], 0.0f);

    for (int k0 = 0; k0 < K; k0 += 32) {
        // stage A tile [128 x 32] (tf32-rounded)
#pragma unroll 4
        for (int i = tid; i < 128 * 32; i += 256) {
            const int r = i >> 5, c = i & 31;
            const int kk = k0 + c;
            float v = 0.f;
            if (CONCAT) {
                if (kk < K1)      v = A[(size_t)(m0 + r) * lda + kk];
                else if (kk < K)  v = A2[(size_t)(m0 + r) * 256 + (kk - K1)];
            } else {
                if (kk < K)       v = A[(size_t)(m0 + r) * lda + kk];
            }
            sA[r * LDA_S + c] = to_tf32(v);
        }
        // stage B tile [32 x 128]
#pragma unroll 4
        for (int i = tid; i < 32 * 128; i += 256) {
            const int r = i >> 7, c = i & 127;
            const int kk = k0 + r;
            sB[r * LDB_S + c] = (kk < K) ? to_tf32(B[(size_t)kk * 256 + n0 + c]) : 0.f;
        }
        __syncthreads();

#pragma unroll
        for (int ks = 0; ks < 32; ks += 8) {
            wmma::fragment<wmma::matrix_a, 16, 16, 8, wmma::precision::tf32, wmma::row_major> fa[2];
            wmma::fragment<wmma::matrix_b, 16, 16, 8, wmma::precision::tf32, wmma::row_major> fb[4];
#pragma unroll
            for (int i = 0; i < 2; i++)
                wmma::load_matrix_sync(fa[i], &sA[(warp_m * 32 + i * 16) * LDA_S + ks], LDA_S);
#pragma unroll
            for (int j = 0; j < 4; j++)
                wmma::load_matrix_sync(fb[j], &sB[ks * LDB_S + warp_n * 64 + j * 16], LDB_S);
#pragma unroll
            for (int i = 0; i < 2; i++)
#pragma unroll
                for (int j = 0; j < 4; j++)
                    wmma::mma_sync(acc[i][j], fa[i], fb[j], acc[i][j]);
        }
        __syncthreads();
    }

    // epilogue: per-warp staging (aliases sA/sB — all compute finished)
    float* sC = smem + wid * (16 * LDC_S);
#pragma unroll
    for (int fm = 0; fm < 2; fm++) {
#pragma unroll
        for (int j = 0; j < 4; j++)
            wmma::store_matrix_sync(sC + j * 16, acc[fm][j], LDC_S, wmma::mem_row_major);
        __syncwarp();

        const int mbase = m0 + warp_m * 32 + fm * 16;
        const int nbase = n0 + warp_n * 64;
#pragma unroll
        for (int q = lane; q < 256; q += 32) {
            const int r  = q >> 4;
            const int c4 = (q & 15) * 4;
            float4 v = *(float4*)&sC[r * LDC_S + c4];
            const size_t m = (size_t)(mbase + r);
            const int n = nbase + c4;
            if (HAS_D)    v = f4add(v, *(const float4*)&D[m * 256 + n]);
            if (HAS_BIAS) v = f4add(v, *(const float4*)&bias[n]);
            if (HAS_RAW)  *(float4*)&raw[m * 256 + n] = v;
            if (RELU) {
                v.x = fmaxf(v.x, 0.f); v.y = fmaxf(v.y, 0.f);
                v.z = fmaxf(v.z, 0.f); v.w = fmaxf(v.w, 0.f);
            }
            *(float4*)&out[m * 256 + n] = v;
        }
        __syncwarp();
    }
}

// ---------------------------------------------------------------------------
// Bond attention gather: one warp per bond.
// ---------------------------------------------------------------------------
__global__ void __launch_bounds__(256) bond_attn(
    const float* __restrict__ msg, const int* __restrict__ bgraph,
    const float* __restrict__ wma, float* __restrict__ agg)
{
    const int gw   = (blockIdx.x * 256 + threadIdx.x) >> 5;
    const int lane = threadIdx.x & 31;
    if (gw >= E_BONDS) return;

    const float4 w0 = *(const float4*)&wma[lane * 8];
    const float4 w1 = *(const float4*)&wma[lane * 8 + 4];

    float4 r0[6], r1[6];
    float  s[6];
#pragma unroll
    for (int j = 0; j < 6; j++) {
        const int nb = bgraph[gw * 6 + j];
        const float4* p = (const float4*)(msg + (size_t)nb * 256) + lane * 2;
        r0[j] = p[0]; r1[j] = p[1];
        float d = f4dot(r0[j], w0) + f4dot(r1[j], w1);
#pragma unroll
        for (int o = 16; o > 0; o >>= 1) d += __shfl_xor_sync(0xffffffffu, d, o);
        s[j] = d;
    }
    float mx = s[0];
#pragma unroll
    for (int j = 1; j < 6; j++) mx = fmaxf(mx, s[j]);
    float e[6], sum = 0.f;
#pragma unroll
    for (int j = 0; j < 6; j++) { e[j] = expf(s[j] - mx); sum += e[j]; }
    const float inv = 1.0f / sum;

    float4 a0 = make_float4(0, 0, 0, 0), a1 = make_float4(0, 0, 0, 0);
#pragma unroll
    for (int j = 0; j < 6; j++) {
        const float w = e[j] * inv;
        a0 = f4fma(w, r0[j], a0);
        a1 = f4fma(w, r1[j], a1);
    }
    float4* o = (float4*)(agg + (size_t)gw * 256) + lane * 2;
    o[0] = a0; o[1] = a1;
}

// ---------------------------------------------------------------------------
__global__ void __launch_bounds__(256) atom_gather(
    const float* __restrict__ msg, const int* __restrict__ agraph,
    float* __restrict__ neia)
{
    const int ga   = (blockIdx.x * 256 + threadIdx.x) >> 5;
    const int lane = threadIdx.x & 31;
    if (ga >= N_ATOMS_) return;

    float4 a0 = make_float4(0, 0, 0, 0), a1 = make_float4(0, 0, 0, 0);
#pragma unroll
    for (int j = 0; j < 6; j++) {
        const int nb = agraph[ga * 6 + j];
        const float4* p = (const float4*)(msg + (size_t)nb * 256) + lane * 2;
        a0 = f4add(a0, p[0]);
        a1 = f4add(a1, p[1]);
    }
    float4* o = (float4*)(neia + (size_t)ga * 256) + lane * 2;
    o[0] = a0; o[1] = a1;
}

// ---------------------------------------------------------------------------
// Per-molecule self-attention: scores = (hW) h^T, softmax rows, t = att @ h
// ---------------------------------------------------------------------------
#define PAD 257
#define MOLATTN_SMEM ((2 * 32 * PAD + 32 * 32) * (int)sizeof(float))

__global__ void __launch_bounds__(256) mol_attn(
    const float* __restrict__ atomh, const float* __restrict__ hW,
    float* __restrict__ t)
{
    extern __shared__ float sm[];
    float* sh = sm;
    float* sw = sm + 32 * PAD;
    float* sa = sm + 2 * 32 * PAD;

    const int b = blockIdx.x, tid = threadIdx.x;
    const float* hb = atomh + (size_t)b * 32 * 256;
    const float* wb = hW    + (size_t)b * 32 * 256;

    for (int i = tid; i < 32 * 256; i += 256) {
        const int a = i >> 8, k = i & 255;
        sh[a * PAD + k] = hb[i];
        sw[a * PAD + k] = wb[i];
    }
    __syncthreads();

    for (int p = tid; p < 1024; p += 256) {
        const int a = p >> 5, c = p & 31;
        float s = 0.f;
#pragma unroll 8
        for (int k = 0; k < 256; k++) s += sw[a * PAD + k] * sh[c * PAD + k];
        sa[a * 32 + c] = s;
    }
    __syncthreads();

    const int wid = tid >> 5, lane = tid & 31;
    for (int a = wid; a < 32; a += 8) {
        float v = sa[a * 32 + lane];
        float m = v;
#pragma unroll
        for (int o = 16; o > 0; o >>= 1) m = fmaxf(m, __shfl_xor_sync(0xffffffffu, m, o));
        float ev = expf(v - m);
        float sum = ev;
#pragma unroll
        for (int o = 16; o > 0; o >>= 1) sum += __shfl_xor_sync(0xffffffffu, sum, o);
        sa[a * 32 + lane] = ev / sum;
    }
    __syncthreads();

    const int k = tid;
    float acc[32];
#pragma unroll
    for (int a = 0; a < 32; a++) acc[a] = 0.f;
    for (int c = 0; c < 32; c++) {
        const float hv = sh[c * PAD + k];
#pragma unroll
        for (int a = 0; a < 32; a++) acc[a] += sa[a * 32 + c] * hv;
    }
#pragma unroll
    for (int a = 0; a < 32; a++)
        t[((size_t)b * 32 + a) * 256 + k] = acc[a];
}

// ---------------------------------------------------------------------------
__global__ void __launch_bounds__(256) mol_reduce(
    const float* __restrict__ atomh, const float* __restrict__ atth,
    float* __restrict__ out)
{
    const int b = blockIdx.x, k = threadIdx.x;
    const float* ph = atomh + (size_t)b * 32 * 256 + k;
    const float* pa = atth  + (size_t)b * 32 * 256 + k;
    float s = 0.f;
#pragma unroll
    for (int a = 0; a < 32; a++) s += ph[a * 256] + pa[a * 256];
    out[(size_t)b * 256 + k] = s * (1.0f / 32.0f);
}

// ---------------------------------------------------------------------------
extern "C" void kernel_launch(void* const* d_in, const int* in_sizes, int n_in,
                              void* d_out, int out_size)
{
    const float* fatoms = (const float*)d_in[0];
    const float* fbonds = (const float*)d_in[1];
    const int*   agraph = (const int*)d_in[2];
    const int*   bgraph = (const int*)d_in[3];
    const float* W_i    = (const float*)d_in[5];
    const float* W_h    = (const float*)d_in[6];
    const float* W_o_w  = (const float*)d_in[7];
    const float* W_o_b  = (const float*)d_in[8];
    const float* W_a    = (const float*)d_in[9];
    const float* W_b_w  = (const float*)d_in[10];
    const float* W_b_b  = (const float*)d_in[11];
    const float* W_ma1  = (const float*)d_in[12];
    float* out = (float*)d_out;

    float* scratch = nullptr;
    cudaGetSymbolAddress((void**)&scratch, g_scratch);
    float* binput  = scratch;
    float* message = binput  + EH;
    float* agg     = message + EH;
    float* neia    = agg     + EH;
    float* atomh   = neia    + NH;
    float* tmp     = atomh   + NH;
    float* tbuf    = tmp     + NH;

    cudaFuncSetAttribute(mol_attn, cudaFuncAttributeMaxDynamicSharedMemorySize,
                         MOLATTN_SMEM);

    const dim3 gridE(E_BONDS / 128, 2);
    const dim3 gridN(N_ATOMS_ / 128, 2);

    // G1: binput = fbonds @ W_i ; message = relu(binput)
    tgemm128<false, false, false, true, true><<<gridE, 256>>>(
        E_BONDS, KIN, 0, fbonds, KIN, nullptr, W_i, nullptr, nullptr, message, binput);

    // 3 message-passing iterations
    for (int it = 0; it < 3; it++) {
        bond_attn<<<E_BONDS / 8, 256>>>(message, bgraph, W_ma1, agg);
        tgemm128<false, true, false, true, false><<<gridE, 256>>>(
            E_BONDS, HID, 0, agg, HID, nullptr, W_h, binput, nullptr, message, nullptr);
    }

    // atom readout: atom_h = relu([fatoms, neia] @ W_o_w + b) fused concat GEMM
    atom_gather<<<N_ATOMS_ / 8, 256>>>(message, agraph, neia);
    tgemm128<true, false, true, true, false><<<gridN, 256>>>(
        N_ATOMS_, KCAT, AFD, fatoms, AFD, neia, W_o_w, nullptr, W_o_b, atomh, nullptr);

    // molecule self-attention pooling
    tgemm128<false, false, false, false, false><<<gridN, 256>>>(
        N_ATOMS_, HID, 0, atomh, HID, nullptr, W_a, nullptr, nullptr, tmp, nullptr);  // hW
    mol_attn<<<BMOL, 256, MOLATTN_SMEM>>>(atomh, tmp, tbuf);                          // t
    tgemm128<false, false, true, true, false><<<gridN, 256>>>(
        N_ATOMS_, HID, 0, tbuf, HID, nullptr, W_b_w, nullptr, W_b_b, tmp, nullptr);   // att_h
    mol_reduce<<<BMOL, 256>>>(atomh, tmp, out);
}

// round 4
// speedup vs baseline: 2.8368x; 2.8368x over previous
#include <cuda_runtime.h>
#include <cuda_fp16.h>
#include <cstdint>
#include <math.h>

#define E_BONDS   131072
#define N_ATOMS_  65536
#define HID       256
#define AFD       143
#define KIN       157
#define KCAT      399
#define BMOL      2048

#define EH  ((size_t)E_BONDS * HID)
#define NH  ((size_t)N_ATOMS_ * HID)
// fp32 buffers + fp16 weight area (1324*256 halves = 169472 floats)
#define WHALF_FLOATS 200000
__device__ float g_scratch[3 * EH + 4 * NH + WHALF_FLOATS];

__device__ __forceinline__ uint32_t smem_u32(const void* p) {
    uint32_t a;
    asm("{ .reg .u64 t; cvta.to.shared.u64 t, %1; cvt.u32.u64 %0, t; }"
        : "=r"(a) : "l"(p));
    return a;
}

// ---------------------------------------------------------------------------
// weights fp32 -> fp16
// ---------------------------------------------------------------------------
__global__ void w2h(const float* __restrict__ src, __half* __restrict__ dst, int n)
{
    int i = blockIdx.x * 256 + threadIdx.x;
    if (i < n) dst[i] = __float2half(src[i]);
}

// ---------------------------------------------------------------------------
// fp16 HMMA GEMM: C[M,256] = A[M,K](fp32) @ B[K,256](fp16) (+D)(+bias)(relu)(raw)
// Block tile 128x128 (grid.y = 2), 256 threads, warp tile 32x64, K-chunk 64.
// ---------------------------------------------------------------------------
#define LDA_H 72     // 64 + 8 pad (halves)
#define LDB_H 136    // 128 + 8 pad

template<bool VECA, bool CONCAT, bool HAS_D, bool HAS_BIAS, bool RELU, bool HAS_RAW>
__global__ void __launch_bounds__(256, 2) hgemm(
    int M, int K, int K1,
    const float* __restrict__ A, int lda,
    const float* __restrict__ A2,          // concat tail, ld 256
    const __half* __restrict__ B,          // [K][256]
    const float* __restrict__ D,
    const float* __restrict__ bias,
    float* __restrict__ out,
    float* __restrict__ raw)
{
    __shared__ __align__(16) __half sA[128 * LDA_H];
    __shared__ __align__(16) __half sB[64 * LDB_H];

    const int tid  = threadIdx.x;
    const int wid  = tid >> 5;
    const int lane = tid & 31;
    const int m0   = blockIdx.x * 128;
    const int n0   = blockIdx.y * 128;
    const int wm   = (wid & 3) * 32;       // warp m offset
    const int wn   = (wid >> 2) * 64;      // warp n offset

    float acc[2][8][4];
#pragma unroll
    for (int t = 0; t < 2; t++)
#pragma unroll
        for (int j = 0; j < 8; j++)
#pragma unroll
            for (int q = 0; q < 4; q++) acc[t][j][q] = 0.f;

    // ldmatrix lane addressing: row = lane%16, col-offset = (lane>>4)*8
    const int lrow = lane & 15;
    const int lcof = (lane >> 4) * 8;

    for (int k0 = 0; k0 < K; k0 += 64) {
        // ---- stage A [128 x 64] fp32 -> fp16 (8 halves per thread-iter) ----
#pragma unroll
        for (int it = 0; it < 4; it++) {
            const int id = tid + it * 256;          // 0..1023
            const int r  = id >> 3;
            const int c8 = (id & 7) * 8;
            __align__(16) __half hb[8];
            if (VECA) {
                const float4 v0 = *(const float4*)&A[(size_t)(m0 + r) * lda + k0 + c8];
                const float4 v1 = *(const float4*)&A[(size_t)(m0 + r) * lda + k0 + c8 + 4];
                hb[0] = __float2half(v0.x); hb[1] = __float2half(v0.y);
                hb[2] = __float2half(v0.z); hb[3] = __float2half(v0.w);
                hb[4] = __float2half(v1.x); hb[5] = __float2half(v1.y);
                hb[6] = __float2half(v1.z); hb[7] = __float2half(v1.w);
            } else {
#pragma unroll
                for (int e = 0; e < 8; e++) {
                    const int kk = k0 + c8 + e;
                    float v = 0.f;
                    if (CONCAT) {
                        if (kk < K1)     v = A[(size_t)(m0 + r) * lda + kk];
                        else if (kk < K) v = A2[(size_t)(m0 + r) * 256 + (kk - K1)];
                    } else if (kk < K)   v = A[(size_t)(m0 + r) * lda + kk];
                    hb[e] = __float2half(v);
                }
            }
            *(uint4*)&sA[r * LDA_H + c8] = *(uint4*)hb;
        }
        // ---- stage B [64 x 128] fp16 ----
#pragma unroll
        for (int it = 0; it < 4; it++) {
            const int id = tid + it * 256;          // 0..1023
            const int r  = id >> 4;                 // 0..63
            const int c8 = (id & 15) * 8;           // 0..120
            uint4 v = make_uint4(0, 0, 0, 0);
            const int kk = k0 + r;
            if (kk < K) v = *(const uint4*)&B[(size_t)kk * 256 + n0 + c8];
            *(uint4*)&sB[r * LDB_H + c8] = v;
        }
        __syncthreads();

        // ---- mma ----
#pragma unroll
        for (int ks = 0; ks < 4; ks++) {
            uint32_t fa[2][4];
#pragma unroll
            for (int t = 0; t < 2; t++) {
                const uint32_t ad = smem_u32(&sA[(wm + t * 16 + lrow) * LDA_H + ks * 16 + lcof]);
                asm volatile("ldmatrix.sync.aligned.m8n8.x4.shared.b16 {%0,%1,%2,%3}, [%4];"
                             : "=r"(fa[t][0]), "=r"(fa[t][1]), "=r"(fa[t][2]), "=r"(fa[t][3])
                             : "r"(ad));
            }
            uint32_t fb[8][2];
#pragma unroll
            for (int nt = 0; nt < 4; nt++) {
                const uint32_t ad = smem_u32(&sB[(ks * 16 + lrow) * LDB_H + wn + nt * 16 + lcof]);
                uint32_t r0, r1, r2, r3;
                asm volatile("ldmatrix.sync.aligned.m8n8.x4.trans.shared.b16 {%0,%1,%2,%3}, [%4];"
                             : "=r"(r0), "=r"(r1), "=r"(r2), "=r"(r3) : "r"(ad));
                fb[nt * 2][0] = r0; fb[nt * 2][1] = r1;
                fb[nt * 2 + 1][0] = r2; fb[nt * 2 + 1][1] = r3;
            }
#pragma unroll
            for (int t = 0; t < 2; t++)
#pragma unroll
                for (int j = 0; j < 8; j++)
                    asm volatile(
                        "mma.sync.aligned.m16n8k16.row.col.f32.f16.f16.f32 "
                        "{%0,%1,%2,%3}, {%4,%5,%6,%7}, {%8,%9}, {%0,%1,%2,%3};"
                        : "+f"(acc[t][j][0]), "+f"(acc[t][j][1]),
                          "+f"(acc[t][j][2]), "+f"(acc[t][j][3])
                        : "r"(fa[t][0]), "r"(fa[t][1]), "r"(fa[t][2]), "r"(fa[t][3]),
                          "r"(fb[j][0]), "r"(fb[j][1]));
        }
        __syncthreads();
    }

    // ---- epilogue ----
#pragma unroll
    for (int t = 0; t < 2; t++) {
        const int mrow = m0 + wm + t * 16 + (lane >> 2);
#pragma unroll
        for (int j = 0; j < 8; j++) {
            const int nc = n0 + wn + j * 8 + (lane & 3) * 2;
#pragma unroll
            for (int half_ = 0; half_ < 2; half_++) {
                const size_t m = (size_t)(mrow + half_ * 8);
                float vx = acc[t][j][half_ * 2 + 0];
                float vy = acc[t][j][half_ * 2 + 1];
                if (HAS_D) {
                    const float2 d = *(const float2*)&D[m * 256 + nc];
                    vx += d.x; vy += d.y;
                }
                if (HAS_BIAS) { vx += bias[nc]; vy += bias[nc + 1]; }
                if (HAS_RAW) *(float2*)&raw[m * 256 + nc] = make_float2(vx, vy);
                if (RELU) { vx = fmaxf(vx, 0.f); vy = fmaxf(vy, 0.f); }
                *(float2*)&out[m * 256 + nc] = make_float2(vx, vy);
            }
        }
    }
}

// ---------------------------------------------------------------------------
// float4 helpers
// ---------------------------------------------------------------------------
__device__ __forceinline__ float4 f4add(float4 a, float4 b) {
    return make_float4(a.x + b.x, a.y + b.y, a.z + b.z, a.w + b.w);
}
__device__ __forceinline__ float4 f4fma(float s, float4 a, float4 acc) {
    acc.x += s * a.x; acc.y += s * a.y; acc.z += s * a.z; acc.w += s * a.w;
    return acc;
}
__device__ __forceinline__ float f4dot(float4 a, float4 b) {
    return a.x * b.x + a.y * b.y + a.z * b.z + a.w * b.w;
}

// ---------------------------------------------------------------------------
// Bond attention gather: one warp per bond.
// ---------------------------------------------------------------------------
__global__ void __launch_bounds__(256) bond_attn(
    const float* __restrict__ msg, const int* __restrict__ bgraph,
    const float* __restrict__ wma, float* __restrict__ agg)
{
    const int gw   = (blockIdx.x * 256 + threadIdx.x) >> 5;
    const int lane = threadIdx.x & 31;
    if (gw >= E_BONDS) return;

    const float4 w0 = *(const float4*)&wma[lane * 8];
    const float4 w1 = *(const float4*)&wma[lane * 8 + 4];

    float4 r0[6], r1[6];
    float  s[6];
#pragma unroll
    for (int j = 0; j < 6; j++) {
        const int nb = bgraph[gw * 6 + j];
        const float4* p = (const float4*)(msg + (size_t)nb * 256) + lane * 2;
        r0[j] = p[0]; r1[j] = p[1];
        float d = f4dot(r0[j], w0) + f4dot(r1[j], w1);
#pragma unroll
        for (int o = 16; o > 0; o >>= 1) d += __shfl_xor_sync(0xffffffffu, d, o);
        s[j] = d;
    }
    float mx = s[0];
#pragma unroll
    for (int j = 1; j < 6; j++) mx = fmaxf(mx, s[j]);
    float e[6], sum = 0.f;
#pragma unroll
    for (int j = 0; j < 6; j++) { e[j] = expf(s[j] - mx); sum += e[j]; }
    const float inv = 1.0f / sum;

    float4 a0 = make_float4(0, 0, 0, 0), a1 = make_float4(0, 0, 0, 0);
#pragma unroll
    for (int j = 0; j < 6; j++) {
        const float w = e[j] * inv;
        a0 = f4fma(w, r0[j], a0);
        a1 = f4fma(w, r1[j], a1);
    }
    float4* o = (float4*)(agg + (size_t)gw * 256) + lane * 2;
    o[0] = a0; o[1] = a1;
}

__global__ void __launch_bounds__(256) atom_gather(
    const float* __restrict__ msg, const int* __restrict__ agraph,
    float* __restrict__ neia)
{
    const int ga   = (blockIdx.x * 256 + threadIdx.x) >> 5;
    const int lane = threadIdx.x & 31;
    if (ga >= N_ATOMS_) return;

    float4 a0 = make_float4(0, 0, 0, 0), a1 = make_float4(0, 0, 0, 0);
#pragma unroll
    for (int j = 0; j < 6; j++) {
        const int nb = agraph[ga * 6 + j];
        const float4* p = (const float4*)(msg + (size_t)nb * 256) + lane * 2;
        a0 = f4add(a0, p[0]);
        a1 = f4add(a1, p[1]);
    }
    float4* o = (float4*)(neia + (size_t)ga * 256) + lane * 2;
    o[0] = a0; o[1] = a1;
}

// ---------------------------------------------------------------------------
// Per-molecule self-attention
// ---------------------------------------------------------------------------
#define PAD 257
#define MOLATTN_SMEM ((2 * 32 * PAD + 32 * 32) * (int)sizeof(float))

__global__ void __launch_bounds__(256) mol_attn(
    const float* __restrict__ atomh, const float* __restrict__ hW,
    float* __restrict__ t)
{
    extern __shared__ float sm[];
    float* sh = sm;
    float* sw = sm + 32 * PAD;
    float* sa = sm + 2 * 32 * PAD;

    const int b = blockIdx.x, tid = threadIdx.x;
    const float* hb = atomh + (size_t)b * 32 * 256;
    const float* wb = hW    + (size_t)b * 32 * 256;

    for (int i = tid; i < 32 * 256; i += 256) {
        const int a = i >> 8, k = i & 255;
        sh[a * PAD + k] = hb[i];
        sw[a * PAD + k] = wb[i];
    }
    __syncthreads();

    for (int p = tid; p < 1024; p += 256) {
        const int a = p >> 5, c = p & 31;
        float s = 0.f;
#pragma unroll 8
        for (int k = 0; k < 256; k++) s += sw[a * PAD + k] * sh[c * PAD + k];
        sa[a * 32 + c] = s;
    }
    __syncthreads();

    const int wid = tid >> 5, lane = tid & 31;
    for (int a = wid; a < 32; a += 8) {
        float v = sa[a * 32 + lane];
        float m = v;
#pragma unroll
        for (int o = 16; o > 0; o >>= 1) m = fmaxf(m, __shfl_xor_sync(0xffffffffu, m, o));
        float ev = expf(v - m);
        float sum = ev;
#pragma unroll
        for (int o = 16; o > 0; o >>= 1) sum += __shfl_xor_sync(0xffffffffu, sum, o);
        sa[a * 32 + lane] = ev / sum;
    }
    __syncthreads();

    const int k = tid;
    float acc[32];
#pragma unroll
    for (int a = 0; a < 32; a++) acc[a] = 0.f;
    for (int c = 0; c < 32; c++) {
        const float hv = sh[c * PAD + k];
#pragma unroll
        for (int a = 0; a < 32; a++) acc[a] += sa[a * 32 + c] * hv;
    }
#pragma unroll
    for (int a = 0; a < 32; a++)
        t[((size_t)b * 32 + a) * 256 + k] = acc[a];
}

__global__ void __launch_bounds__(256) mol_reduce(
    const float* __restrict__ atomh, const float* __restrict__ atth,
    float* __restrict__ out)
{
    const int b = blockIdx.x, k = threadIdx.x;
    const float* ph = atomh + (size_t)b * 32 * 256 + k;
    const float* pa = atth  + (size_t)b * 32 * 256 + k;
    float s = 0.f;
#pragma unroll
    for (int a = 0; a < 32; a++) s += ph[a * 256] + pa[a * 256];
    out[(size_t)b * 256 + k] = s * (1.0f / 32.0f);
}

// ---------------------------------------------------------------------------
extern "C" void kernel_launch(void* const* d_in, const int* in_sizes, int n_in,
                              void* d_out, int out_size)
{
    const float* fatoms = (const float*)d_in[0];
    const float* fbonds = (const float*)d_in[1];
    const int*   agraph = (const int*)d_in[2];
    const int*   bgraph = (const int*)d_in[3];
    const float* W_i    = (const float*)d_in[5];
    const float* W_h    = (const float*)d_in[6];
    const float* W_o_w  = (const float*)d_in[7];
    const float* W_o_b  = (const float*)d_in[8];
    const float* W_a    = (const float*)d_in[9];
    const float* W_b_w  = (const float*)d_in[10];
    const float* W_b_b  = (const float*)d_in[11];
    const float* W_ma1  = (const float*)d_in[12];
    float* out = (float*)d_out;

    float* scratch = nullptr;
    cudaGetSymbolAddress((void**)&scratch, g_scratch);
    float* binput  = scratch;
    float* message = binput  + EH;
    float* agg     = message + EH;
    float* neia    = agg     + EH;
    float* atomh   = neia    + NH;
    float* tmp     = atomh   + NH;
    float* tbuf    = tmp     + NH;
    __half* Wi_h = (__half*)(tbuf + NH);
    __half* Wh_h = Wi_h + KIN  * 256;
    __half* Wo_h = Wh_h + HID  * 256;
    __half* Wa_h = Wo_h + KCAT * 256;
    __half* Wb_h = Wa_h + HID  * 256;

    cudaFuncSetAttribute(mol_attn, cudaFuncAttributeMaxDynamicSharedMemorySize,
                         MOLATTN_SMEM);

    // pre-convert weights to fp16
    w2h<<<(KIN  * 256 + 255) / 256, 256>>>(W_i,   Wi_h, KIN  * 256);
    w2h<<<(HID  * 256 + 255) / 256, 256>>>(W_h,   Wh_h, HID  * 256);
    w2h<<<(KCAT * 256 + 255) / 256, 256>>>(W_o_w, Wo_h, KCAT * 256);
    w2h<<<(HID  * 256 + 255) / 256, 256>>>(W_a,   Wa_h, HID  * 256);
    w2h<<<(HID  * 256 + 255) / 256, 256>>>(W_b_w, Wb_h, HID  * 256);

    const dim3 gE(E_BONDS / 128, 2);
    const dim3 gN(N_ATOMS_ / 128, 2);

    // G1: binput = fbonds @ W_i ; message = relu(binput)   (K=157, scalar A)
    hgemm<false, false, false, false, true, true><<<gE, 256>>>(
        E_BONDS, KIN, 0, fbonds, KIN, nullptr, Wi_h, nullptr, nullptr, message, binput);

    // 3 message-passing iterations (K=256, vector A)
    for (int it = 0; it < 3; it++) {
        bond_attn<<<E_BONDS / 8, 256>>>(message, bgraph, W_ma1, agg);
        hgemm<true, false, true, false, true, false><<<gE, 256>>>(
            E_BONDS, HID, 0, agg, HID, nullptr, Wh_h, binput, nullptr, message, nullptr);
    }

    // atom readout: atom_h = relu([fatoms, neia] @ W_o_w + b)   (K=399 concat)
    atom_gather<<<N_ATOMS_ / 8, 256>>>(message, agraph, neia);
    hgemm<false, true, false, true, true, false><<<gN, 256>>>(
        N_ATOMS_, KCAT, AFD, fatoms, AFD, neia, Wo_h, nullptr, W_o_b, atomh, nullptr);

    // molecule self-attention pooling
    hgemm<true, false, false, false, false, false><<<gN, 256>>>(
        N_ATOMS_, HID, 0, atomh, HID, nullptr, Wa_h, nullptr, nullptr, tmp, nullptr);
    mol_attn<<<BMOL, 256, MOLATTN_SMEM>>>(atomh, tmp, tbuf);
    hgemm<true, false, false, true, true, false><<<gN, 256>>>(
        N_ATOMS_, HID, 0, tbuf, HID, nullptr, Wb_h, nullptr, W_b_b, tmp, nullptr);
    mol_reduce<<<BMOL, 256>>>(atomh, tmp, out);
}

// round 5
// speedup vs baseline: 3.1690x; 1.1171x over previous
#include <cuda_runtime.h>
#include <cuda_fp16.h>
#include <cstdint>
#include <math.h>

#define E_BONDS   131072
#define N_ATOMS_  65536
#define HID       256
#define AFD       143
#define KIN       157
#define KCAT      399
#define BMOL      2048

#define EH  ((size_t)E_BONDS * HID)
#define NH  ((size_t)N_ATOMS_ * HID)
// fp32 units: binput(EH) + message_h(EH/2) + agg_h(EH/2) + neia_h(NH/2)
//           + atomh(NH) + atomh_h(NH/2) + tmp(NH) + tbuf_h(NH/2) + weights
#define WHALF_FLOATS 200000
__device__ float g_scratch[2 * EH + 4 * NH + WHALF_FLOATS];  // 3.5NH rounded up

__device__ __forceinline__ uint32_t smem_u32(const void* p) {
    uint32_t a;
    asm("{ .reg .u64 t; cvta.to.shared.u64 t, %1; cvt.u32.u64 %0, t; }"
        : "=r"(a) : "l"(p));
    return a;
}
__device__ __forceinline__ void cp_async16(uint32_t dst, const void* src) {
    asm volatile("cp.async.cg.shared.global [%0], [%1], 16;"
                 :: "r"(dst), "l"(src));
}
__device__ __forceinline__ void cp_async16_pred(uint32_t dst, const void* src, bool v) {
    int sz = v ? 16 : 0;
    asm volatile("cp.async.cg.shared.global [%0], [%1], 16, %2;"
                 :: "r"(dst), "l"(src), "r"(sz));
}
#define CP_COMMIT() asm volatile("cp.async.commit_group;" ::: "memory")
#define CP_WAIT0()  asm volatile("cp.async.wait_group 0;" ::: "memory")

// ---------------------------------------------------------------------------
__global__ void w2h(const float* __restrict__ src, __half* __restrict__ dst, int n)
{
    int i = blockIdx.x * 256 + threadIdx.x;
    if (i < n) dst[i] = __float2half(src[i]);
}

// ---------------------------------------------------------------------------
// fp16 HMMA GEMM, double-buffered cp.async, K-chunk 32.
// C[M,256] = A[M,K] @ B[K,256]  (+D fp32)(+bias)(relu) -> outf fp32 / outh fp16 / raw fp32
// AMODE: 0 = fp32 scalar A (lda), 1 = fp16 A (ld 256), 2 = concat fp32[0,K1)+fp16[K1,K)
// Block 128x128 (grid.y=2), 256 thr, warp tile 32x64.
// ---------------------------------------------------------------------------
#define LDA_H 40     // 32 + 8 pad halves
#define LDB_H 136    // 128 + 8 pad halves

template<int AMODE, bool HAS_D, bool HAS_BIAS, bool RELU, bool OUTF, bool OUTH, bool RAWF>
__global__ void __launch_bounds__(256, 2) hgemm(
    int M, int K, int K1,
    const float* __restrict__ Af, int lda,
    const __half* __restrict__ Ah,
    const __half* __restrict__ B,
    const float* __restrict__ D,
    const float* __restrict__ bias,
    float* __restrict__ outf,
    __half* __restrict__ outh,
    float* __restrict__ raw)
{
    __shared__ __align__(16) __half sA[2][128 * LDA_H];
    __shared__ __align__(16) __half sB[2][32 * LDB_H];

    const int tid  = threadIdx.x;
    const int wid  = tid >> 5;
    const int lane = tid & 31;
    const int m0   = blockIdx.x * 128;
    const int n0   = blockIdx.y * 128;
    const int wm   = (wid & 3) * 32;
    const int wn   = (wid >> 2) * 64;
    const int S    = (K + 31) >> 5;

    float acc[2][8][4];
#pragma unroll
    for (int t = 0; t < 2; t++)
#pragma unroll
        for (int j = 0; j < 8; j++)
#pragma unroll
            for (int q = 0; q < 4; q++) acc[t][j][q] = 0.f;

    const int lrow = lane & 15;
    const int lcof = (lane >> 4) * 8;

    // ---- stage loader ----
    auto stage = [&](int s, int buf) {
        const int k0 = s * 32;
        // B [32k x 128n]
#pragma unroll
        for (int it = 0; it < 2; it++) {
            const int id = tid + it * 256;          // 0..511
            const int r  = id >> 4;                 // 0..31
            const int c8 = (id & 15) * 8;           // halves 0..120
            const int kk = k0 + r;
            const uint32_t dst = smem_u32(&sB[buf][r * LDB_H + c8]);
            if (AMODE == 1) {
                cp_async16(dst, &B[(size_t)kk * 256 + n0 + c8]);
            } else {
                const bool v = kk < K;
                cp_async16_pred(dst, v ? &B[(size_t)kk * 256 + n0 + c8] : (const void*)B, v);
            }
        }
        // A [128m x 32k]
        if (AMODE == 1) {
#pragma unroll
            for (int it = 0; it < 2; it++) {
                const int id  = tid + it * 256;     // 0..511
                const int r   = id >> 2;            // 0..127
                const int c16 = (id & 3) * 8;       // halves 0..24
                const uint32_t dst = smem_u32(&sA[buf][r * LDA_H + c16]);
                cp_async16(dst, &Ah[(size_t)(m0 + r) * 256 + k0 + c16]);
            }
        } else {
#pragma unroll
            for (int i = tid; i < 128 * 32; i += 256) {
                const int r = i >> 5, c = i & 31;
                const int kk = k0 + c;
                float v = 0.f;
                if (AMODE == 2) {
                    if (kk < K1)     v = Af[(size_t)(m0 + r) * lda + kk];
                    else if (kk < K) {
                        sA[buf][r * LDA_H + c] = Ah[(size_t)(m0 + r) * 256 + (kk - K1)];
                        continue;
                    }
                } else if (kk < K)   v = Af[(size_t)(m0 + r) * lda + kk];
                sA[buf][r * LDA_H + c] = __float2half(v);
            }
        }
        CP_COMMIT();
    };

    stage(0, 0);

    for (int s = 0; s < S; s++) {
        const int buf = s & 1;
        CP_WAIT0();
        __syncthreads();
        if (s + 1 < S) stage(s + 1, buf ^ 1);

        // ---- compute stage s ----
#pragma unroll
        for (int ks = 0; ks < 2; ks++) {
            uint32_t fa[2][4];
#pragma unroll
            for (int t = 0; t < 2; t++) {
                const uint32_t ad = smem_u32(&sA[buf][(wm + t * 16 + lrow) * LDA_H + ks * 16 + lcof]);
                asm volatile("ldmatrix.sync.aligned.m8n8.x4.shared.b16 {%0,%1,%2,%3}, [%4];"
                             : "=r"(fa[t][0]), "=r"(fa[t][1]), "=r"(fa[t][2]), "=r"(fa[t][3])
                             : "r"(ad));
            }
            uint32_t fb[8][2];
#pragma unroll
            for (int nt = 0; nt < 4; nt++) {
                const uint32_t ad = smem_u32(&sB[buf][(ks * 16 + lrow) * LDB_H + wn + nt * 16 + lcof]);
                uint32_t r0, r1, r2, r3;
                asm volatile("ldmatrix.sync.aligned.m8n8.x4.trans.shared.b16 {%0,%1,%2,%3}, [%4];"
                             : "=r"(r0), "=r"(r1), "=r"(r2), "=r"(r3) : "r"(ad));
                fb[nt * 2][0] = r0; fb[nt * 2][1] = r1;
                fb[nt * 2 + 1][0] = r2; fb[nt * 2 + 1][1] = r3;
            }
#pragma unroll
            for (int t = 0; t < 2; t++)
#pragma unroll
                for (int j = 0; j < 8; j++)
                    asm volatile(
                        "mma.sync.aligned.m16n8k16.row.col.f32.f16.f16.f32 "
                        "{%0,%1,%2,%3}, {%4,%5,%6,%7}, {%8,%9}, {%0,%1,%2,%3};"
                        : "+f"(acc[t][j][0]), "+f"(acc[t][j][1]),
                          "+f"(acc[t][j][2]), "+f"(acc[t][j][3])
                        : "r"(fa[t][0]), "r"(fa[t][1]), "r"(fa[t][2]), "r"(fa[t][3]),
                          "r"(fb[j][0]), "r"(fb[j][1]));
        }
    }

    // ---- epilogue ----
#pragma unroll
    for (int t = 0; t < 2; t++) {
        const int mrow = m0 + wm + t * 16 + (lane >> 2);
#pragma unroll
        for (int j = 0; j < 8; j++) {
            const int nc = n0 + wn + j * 8 + (lane & 3) * 2;
#pragma unroll
            for (int hf = 0; hf < 2; hf++) {
                const size_t m = (size_t)(mrow + hf * 8);
                float vx = acc[t][j][hf * 2 + 0];
                float vy = acc[t][j][hf * 2 + 1];
                if (HAS_D) {
                    const float2 d = *(const float2*)&D[m * 256 + nc];
                    vx += d.x; vy += d.y;
                }
                if (HAS_BIAS) { vx += bias[nc]; vy += bias[nc + 1]; }
                if (RAWF) *(float2*)&raw[m * 256 + nc] = make_float2(vx, vy);
                if (RELU) { vx = fmaxf(vx, 0.f); vy = fmaxf(vy, 0.f); }
                if (OUTF) *(float2*)&outf[m * 256 + nc] = make_float2(vx, vy);
                if (OUTH) *(__half2*)&outh[m * 256 + nc] = __floats2half2_rn(vx, vy);
            }
        }
    }
}

// ---------------------------------------------------------------------------
// Bond attention gather (fp16 messages): one warp per bond.
// ---------------------------------------------------------------------------
__global__ void __launch_bounds__(256) bond_attn(
    const __half* __restrict__ msg, const int* __restrict__ bgraph,
    const float* __restrict__ wma, float* __restrict__ dummy, __half* __restrict__ agg)
{
    const int gw   = (blockIdx.x * 256 + threadIdx.x) >> 5;
    const int lane = threadIdx.x & 31;
    if (gw >= E_BONDS) return;

    const float4 w0 = *(const float4*)&wma[lane * 8];
    const float4 w1 = *(const float4*)&wma[lane * 8 + 4];

    uint4  rv[6];
    float  s[6];
#pragma unroll
    for (int j = 0; j < 6; j++) {
        const int nb = bgraph[gw * 6 + j];
        rv[j] = *(const uint4*)(msg + (size_t)nb * 256 + lane * 8);
        const float2 f0 = __half22float2(*(const __half2*)&rv[j].x);
        const float2 f1 = __half22float2(*(const __half2*)&rv[j].y);
        const float2 f2 = __half22float2(*(const __half2*)&rv[j].z);
        const float2 f3 = __half22float2(*(const __half2*)&rv[j].w);
        float d = f0.x * w0.x + f0.y * w0.y + f1.x * w0.z + f1.y * w0.w
                + f2.x * w1.x + f2.y * w1.y + f3.x * w1.z + f3.y * w1.w;
#pragma unroll
        for (int o = 16; o > 0; o >>= 1) d += __shfl_xor_sync(0xffffffffu, d, o);
        s[j] = d;
    }
    float mx = s[0];
#pragma unroll
    for (int j = 1; j < 6; j++) mx = fmaxf(mx, s[j]);
    float e[6], sum = 0.f;
#pragma unroll
    for (int j = 0; j < 6; j++) { e[j] = expf(s[j] - mx); sum += e[j]; }
    const float inv = 1.0f / sum;

    float a[8] = {0, 0, 0, 0, 0, 0, 0, 0};
#pragma unroll
    for (int j = 0; j < 6; j++) {
        const float w = e[j] * inv;
        const float2 f0 = __half22float2(*(const __half2*)&rv[j].x);
        const float2 f1 = __half22float2(*(const __half2*)&rv[j].y);
        const float2 f2 = __half22float2(*(const __half2*)&rv[j].z);
        const float2 f3 = __half22float2(*(const __half2*)&rv[j].w);
        a[0] += w * f0.x; a[1] += w * f0.y; a[2] += w * f1.x; a[3] += w * f1.y;
        a[4] += w * f2.x; a[5] += w * f2.y; a[6] += w * f3.x; a[7] += w * f3.y;
    }
    uint4 ov;
    *(__half2*)&ov.x = __floats2half2_rn(a[0], a[1]);
    *(__half2*)&ov.y = __floats2half2_rn(a[2], a[3]);
    *(__half2*)&ov.z = __floats2half2_rn(a[4], a[5]);
    *(__half2*)&ov.w = __floats2half2_rn(a[6], a[7]);
    *(uint4*)(agg + (size_t)gw * 256 + lane * 8) = ov;
}

// ---------------------------------------------------------------------------
__global__ void __launch_bounds__(256) atom_gather(
    const __half* __restrict__ msg, const int* __restrict__ agraph,
    __half* __restrict__ neia)
{
    const int ga   = (blockIdx.x * 256 + threadIdx.x) >> 5;
    const int lane = threadIdx.x & 31;
    if (ga >= N_ATOMS_) return;

    float a[8] = {0, 0, 0, 0, 0, 0, 0, 0};
#pragma unroll
    for (int j = 0; j < 6; j++) {
        const int nb = agraph[ga * 6 + j];
        const uint4 rv = *(const uint4*)(msg + (size_t)nb * 256 + lane * 8);
        const float2 f0 = __half22float2(*(const __half2*)&rv.x);
        const float2 f1 = __half22float2(*(const __half2*)&rv.y);
        const float2 f2 = __half22float2(*(const __half2*)&rv.z);
        const float2 f3 = __half22float2(*(const __half2*)&rv.w);
        a[0] += f0.x; a[1] += f0.y; a[2] += f1.x; a[3] += f1.y;
        a[4] += f2.x; a[5] += f2.y; a[6] += f3.x; a[7] += f3.y;
    }
    uint4 ov;
    *(__half2*)&ov.x = __floats2half2_rn(a[0], a[1]);
    *(__half2*)&ov.y = __floats2half2_rn(a[2], a[3]);
    *(__half2*)&ov.z = __floats2half2_rn(a[4], a[5]);
    *(__half2*)&ov.w = __floats2half2_rn(a[6], a[7]);
    *(uint4*)(neia + (size_t)ga * 256 + lane * 8) = ov;
}

// ---------------------------------------------------------------------------
// Per-molecule self-attention; t output fp16 (feeds Wb GEMM A)
// ---------------------------------------------------------------------------
#define PAD 257
#define MOLATTN_SMEM ((2 * 32 * PAD + 32 * 32) * (int)sizeof(float))

__global__ void __launch_bounds__(256) mol_attn(
    const float* __restrict__ atomh, const float* __restrict__ hW,
    __half* __restrict__ t)
{
    extern __shared__ float sm[];
    float* sh = sm;
    float* sw = sm + 32 * PAD;
    float* sa = sm + 2 * 32 * PAD;

    const int b = blockIdx.x, tid = threadIdx.x;
    const float* hb = atomh + (size_t)b * 32 * 256;
    const float* wb = hW    + (size_t)b * 32 * 256;

    for (int i = tid; i < 32 * 256; i += 256) {
        const int a = i >> 8, k = i & 255;
        sh[a * PAD + k] = hb[i];
        sw[a * PAD + k] = wb[i];
    }
    __syncthreads();

    for (int p = tid; p < 1024; p += 256) {
        const int a = p >> 5, c = p & 31;
        float s = 0.f;
#pragma unroll 8
        for (int k = 0; k < 256; k++) s += sw[a * PAD + k] * sh[c * PAD + k];
        sa[a * 32 + c] = s;
    }
    __syncthreads();

    const int wid = tid >> 5, lane = tid & 31;
    for (int a = wid; a < 32; a += 8) {
        float v = sa[a * 32 + lane];
        float m = v;
#pragma unroll
        for (int o = 16; o > 0; o >>= 1) m = fmaxf(m, __shfl_xor_sync(0xffffffffu, m, o));
        float ev = expf(v - m);
        float sum = ev;
#pragma unroll
        for (int o = 16; o > 0; o >>= 1) sum += __shfl_xor_sync(0xffffffffu, sum, o);
        sa[a * 32 + lane] = ev / sum;
    }
    __syncthreads();

    const int k = tid;
    float acc[32];
#pragma unroll
    for (int a = 0; a < 32; a++) acc[a] = 0.f;
    for (int c = 0; c < 32; c++) {
        const float hv = sh[c * PAD + k];
#pragma unroll
        for (int a = 0; a < 32; a++) acc[a] += sa[a * 32 + c] * hv;
    }
#pragma unroll
    for (int a = 0; a < 32; a++)
        t[((size_t)b * 32 + a) * 256 + k] = __float2half(acc[a]);
}

__global__ void __launch_bounds__(256) mol_reduce(
    const float* __restrict__ atomh, const float* __restrict__ atth,
    float* __restrict__ out)
{
    const int b = blockIdx.x, k = threadIdx.x;
    const float* ph = atomh + (size_t)b * 32 * 256 + k;
    const float* pa = atth  + (size_t)b * 32 * 256 + k;
    float s = 0.f;
#pragma unroll
    for (int a = 0; a < 32; a++) s += ph[a * 256] + pa[a * 256];
    out[(size_t)b * 256 + k] = s * (1.0f / 32.0f);
}

// ---------------------------------------------------------------------------
extern "C" void kernel_launch(void* const* d_in, const int* in_sizes, int n_in,
                              void* d_out, int out_size)
{
    const float* fatoms = (const float*)d_in[0];
    const float* fbonds = (const float*)d_in[1];
    const int*   agraph = (const int*)d_in[2];
    const int*   bgraph = (const int*)d_in[3];
    const float* W_i    = (const float*)d_in[5];
    const float* W_h    = (const float*)d_in[6];
    const float* W_o_w  = (const float*)d_in[7];
    const float* W_o_b  = (const float*)d_in[8];
    const float* W_a    = (const float*)d_in[9];
    const float* W_b_w  = (const float*)d_in[10];
    const float* W_b_b  = (const float*)d_in[11];
    const float* W_ma1  = (const float*)d_in[12];
    float* out = (float*)d_out;

    float* scratch = nullptr;
    cudaGetSymbolAddress((void**)&scratch, g_scratch);
    float*  binput  = scratch;                        // EH f32
    __half* message = (__half*)(binput + EH);         // EH h16 (EH/2 floats)
    __half* agg     = (__half*)(binput + EH + EH/2);  // EH h16
    __half* neia    = (__half*)(binput + 2*EH);       // NH h16 (NH/2 floats)
    float*  atomh   = binput + 2*EH + NH/2;           // NH f32
    __half* atomh_h = (__half*)(atomh + NH);          // NH h16
    float*  tmp     = atomh + NH + NH/2;              // NH f32
    __half* tbuf    = (__half*)(tmp + NH);            // NH h16
    __half* Wi_h    = (__half*)(tmp + NH + NH/2);
    __half* Wh_h = Wi_h + KIN  * 256;
    __half* Wo_h = Wh_h + HID  * 256;
    __half* Wa_h = Wo_h + KCAT * 256;
    __half* Wb_h = Wa_h + HID  * 256;

    cudaFuncSetAttribute(mol_attn, cudaFuncAttributeMaxDynamicSharedMemorySize,
                         MOLATTN_SMEM);

    w2h<<<(KIN  * 256 + 255) / 256, 256>>>(W_i,   Wi_h, KIN  * 256);
    w2h<<<(HID  * 256 + 255) / 256, 256>>>(W_h,   Wh_h, HID  * 256);
    w2h<<<(KCAT * 256 + 255) / 256, 256>>>(W_o_w, Wo_h, KCAT * 256);
    w2h<<<(HID  * 256 + 255) / 256, 256>>>(W_a,   Wa_h, HID  * 256);
    w2h<<<(HID  * 256 + 255) / 256, 256>>>(W_b_w, Wb_h, HID  * 256);

    const dim3 gE(E_BONDS / 128, 2);
    const dim3 gN(N_ATOMS_ / 128, 2);

    // G1: binput(f32,raw) + message(f16,relu) = fbonds @ W_i
    hgemm<0, false, false, true, false, true, true><<<gE, 256>>>(
        E_BONDS, KIN, 0, fbonds, KIN, nullptr, Wi_h, nullptr, nullptr,
        nullptr, message, binput);

    // 3 message-passing iterations
    for (int it = 0; it < 3; it++) {
        bond_attn<<<E_BONDS / 8, 256>>>(message, bgraph, W_ma1, nullptr, agg);
        hgemm<1, true, false, true, false, true, false><<<gE, 256>>>(
            E_BONDS, HID, 0, nullptr, 0, agg, Wh_h, binput, nullptr,
            nullptr, message, nullptr);
    }

    // atom readout: atomh(f32) + atomh_h(f16) = relu([fatoms, neia] @ W_o_w + b)
    atom_gather<<<N_ATOMS_ / 8, 256>>>(message, agraph, neia);
    hgemm<2, false, true, true, true, true, false><<<gN, 256>>>(
        N_ATOMS_, KCAT, AFD, fatoms, AFD, neia, Wo_h, nullptr, W_o_b,
        atomh, atomh_h, nullptr);

    // molecule self-attention pooling
    hgemm<1, false, false, false, true, false, false><<<gN, 256>>>(
        N_ATOMS_, HID, 0, nullptr, 0, atomh_h, Wa_h, nullptr, nullptr,
        tmp, nullptr, nullptr);                                  // hW
    mol_attn<<<BMOL, 256, MOLATTN_SMEM>>>(atomh, tmp, tbuf);     // t (f16)
    hgemm<1, false, true, true, true, false, false><<<gN, 256>>>(
        N_ATOMS_, HID, 0, nullptr, 0, tbuf, Wb_h, nullptr, W_b_b,
        tmp, nullptr, nullptr);                                  // att_h
    mol_reduce<<<BMOL, 256>>>(atomh, tmp, out);
}